// round 5
// baseline (speedup 1.0000x reference)
#include <cuda_runtime.h>
#include <cstdint>

#define NUM_SEG 100000
#define DIM 32
#define TPB 256
#define ROWS_PER_BLK 256
#define CHUNKS_PER_BLK (ROWS_PER_BLK * 8)   // float4 chunks (32 floats = 8/row)

// Scratch: per-segment counts (allocation-free rule => __device__ global)
__device__ float g_counts[NUM_SEG];

__device__ __forceinline__ uint32_t smem_u32(const void* p) {
    uint32_t a;
    asm("{ .reg .u64 t; cvta.to.shared.u64 t, %1; cvt.u32.u64 %0, t; }" : "=r"(a) : "l"(p));
    return a;
}

// Hybrid scatter with INTERLEAVED path selection: within every resident wave,
// ~17/32 blocks push sums through the TMA engine (cp.reduce.async.bulk) and
// ~15/32 through the LSU (red.global.v4), so both engines are concurrently
// loaded. Target: the DRAM read floor.
__global__ void __launch_bounds__(TPB) scatter_kernel(
    const float4* __restrict__ x4,
    const int* __restrict__ index,
    float* __restrict__ out,
    int nrows)
{
    __shared__ float4 tile[CHUNKS_PER_BLK];   // 32 KB (TMA path only)
    __shared__ int segs[ROWS_PER_BLK];        // (RED path only)

    int t = threadIdx.x;
    long long base_chunk = (long long)blockIdx.x * CHUNKS_PER_BLK;
    long long nchunks = (long long)nrows * 8;
    int row0 = blockIdx.x * ROWS_PER_BLK;

    bool use_tma = (blockIdx.x & 31) < 17;   // interleaved within each wave

    if (use_tma) {
        // ---- TMA bulk-reduce path ----
        #pragma unroll
        for (int k = 0; k < 8; k++) {
            long long c = base_chunk + t + k * TPB;
            if (c < nchunks) tile[t + k * TPB] = x4[c];
        }
        __syncthreads();
        asm volatile("fence.proxy.async.shared::cta;" ::: "memory");

        int row = row0 + t;
        if (row < nrows) {
            int seg = index[row];
            if ((unsigned)seg < NUM_SEG) {
                uint32_t saddr = smem_u32(&tile[t * 8]);
                float* gdst = out + (long long)seg * DIM;
                asm volatile(
                    "cp.reduce.async.bulk.global.shared::cta.bulk_group.add.f32 [%0], [%1], %2;"
                    :: "l"(gdst), "r"(saddr), "r"(DIM * 4) : "memory");
                atomicAdd(&g_counts[seg], 1.0f);
            }
        }
        asm volatile("cp.async.bulk.commit_group;" ::: "memory");
        asm volatile("cp.async.bulk.wait_group 0;" ::: "memory");
    } else {
        // ---- LSU red.global path ----
        int row = row0 + t;
        int myseg = -1;
        if (row < nrows) {
            myseg = index[row];
            if ((unsigned)myseg >= NUM_SEG) myseg = -1;
        }
        segs[t] = myseg;
        __syncthreads();

        #pragma unroll
        for (int k = 0; k < 8; k++) {
            long long c = base_chunk + t + k * TPB;
            if (c < nchunks) {
                int local = t + k * TPB;
                int seg = segs[local >> 3];
                if (seg >= 0) {
                    float4 v = x4[c];
                    float* addr = out + (long long)seg * DIM + (local & 7) * 4;
                    asm volatile("red.global.add.v4.f32 [%0], {%1, %2, %3, %4};"
                                 :: "l"(addr), "f"(v.x), "f"(v.y), "f"(v.z), "f"(v.w)
                                 : "memory");
                }
            }
        }
        if (myseg >= 0) atomicAdd(&g_counts[myseg], 1.0f);
    }
}

// Vectorized divide: one thread per float4; reciprocal once per thread.
__global__ void divide_kernel(float4* __restrict__ out4, int total4) {
    int i = blockIdx.x * blockDim.x + threadIdx.x;
    if (i < total4) {
        float c = g_counts[i >> 3];          // 8 float4 per row of 32
        float r = __frcp_rn(fmaxf(c, 1.0f));
        float4 v = out4[i];
        v.x *= r; v.y *= r; v.z *= r; v.w *= r;
        out4[i] = v;
    }
}

extern "C" void kernel_launch(void* const* d_in, const int* in_sizes, int n_in,
                              void* d_out, int out_size) {
    const float4* x4 = (const float4*)d_in[0];
    const int* index = (const int*)d_in[1];
    float* out = (float*)d_out;

    int nrows = in_sizes[1];   // 4,000,000
    int total = out_size;      // NUM_SEG * DIM

    void* counts_ptr = nullptr;
    cudaGetSymbolAddress(&counts_ptr, g_counts);
    cudaMemsetAsync(out, 0, (size_t)total * sizeof(float), 0);
    cudaMemsetAsync(counts_ptr, 0, (size_t)NUM_SEG * sizeof(float), 0);

    int sb = (nrows + ROWS_PER_BLK - 1) / ROWS_PER_BLK;
    scatter_kernel<<<sb, TPB>>>(x4, index, out, nrows);

    int total4 = total / 4;
    int db = (total4 + TPB - 1) / TPB;
    divide_kernel<<<db, TPB>>>((float4*)out, total4);
}